// round 1
// baseline (speedup 1.0000x reference)
#include <cuda_runtime.h>
#include <cstdint>

// ---------------------------------------------------------------------------
// LSAGEDirected: 3 directed mean-aggregation hops (dim 64->128->256->512),
// then out = h3 @ W^T + b  ([50000,512] @ [512,128]).
//
// Strategy:
//   - Detect int32-vs-int64 edge_index layout on device (JAX x64 ambiguity).
//   - Degrees + inverse-degree normalizers via int atomics.
//   - Padded CSR (cap 96) per direction, built with atomic cursors.
//   - Pull aggregation: one warp per (node, direction), coalesced row gathers.
//     Sources fit in L2 -> L2-BW-bound, no float atomics anywhere.
//   - fp32 tiled SGEMM for the final projection.
// ---------------------------------------------------------------------------

#define NN 50000
#define NE 800000
#define CAP 96          // max padded degree (Poisson(16) tail; huge margin)
#define IND 64
#define KDIM 512
#define ODIM 128

// ---- static device scratch (allocation-free rule) ----
__device__ int   g_deg_in [NN];
__device__ int   g_deg_out[NN];
__device__ int   g_cur_in [NN];
__device__ int   g_cur_out[NN];
__device__ float g_inv_in [NN];
__device__ float g_inv_out[NN];
__device__ int   g_csr_in [(size_t)NN * CAP];
__device__ int   g_csr_out[(size_t)NN * CAP];
__device__ float g_h1[(size_t)NN * 128];
__device__ float g_h2[(size_t)NN * 256];
__device__ float g_h3[(size_t)NN * 512];
__device__ int   g_is64;

// ---------------------------------------------------------------------------
__global__ void zero_kernel(int n) {
    int i = blockIdx.x * blockDim.x + threadIdx.x;
    if (i < n) {
        g_deg_in[i] = 0; g_deg_out[i] = 0;
        g_cur_in[i] = 0; g_cur_out[i] = 0;
    }
    if (i == 0) g_is64 = 1;   // assume int64 until proven otherwise
}

// If edge data is int32, some odd 32-bit word (a real index) is nonzero.
// If it is int64 (<2^31 values), every checked odd word is a zero high-half.
// Reads stay within min(int32,int64) buffer extent: max index 2*E-1.
__global__ void detect_kernel(const int* __restrict__ p, int E) {
    int i = blockIdx.x * blockDim.x + threadIdx.x;
    int stride = gridDim.x * blockDim.x;
    for (; i < E; i += stride) {
        if (p[2 * i + 1] != 0) { g_is64 = 0; return; }
    }
}

__device__ __forceinline__ void load_edge(const int* p, int e, int E, int is64,
                                          int& s, int& d) {
    if (is64) { s = p[2 * e]; d = p[2 * E + 2 * e]; }
    else      { s = p[e];     d = p[E + e]; }
}

__global__ void degree_kernel(const int* __restrict__ p, int E) {
    int is64 = g_is64;
    int i = blockIdx.x * blockDim.x + threadIdx.x;
    int stride = gridDim.x * blockDim.x;
    for (; i < E; i += stride) {
        int s, d; load_edge(p, i, E, is64, s, d);
        atomicAdd(&g_deg_in[d], 1);
        atomicAdd(&g_deg_out[s], 1);
    }
}

__global__ void inv_kernel(int n) {
    int i = blockIdx.x * blockDim.x + threadIdx.x;
    if (i < n) {
        g_inv_in[i]  = 1.0f / (float)max(g_deg_in[i], 1);
        g_inv_out[i] = 1.0f / (float)max(g_deg_out[i], 1);
    }
}

__global__ void csr_kernel(const int* __restrict__ p, int E) {
    int is64 = g_is64;
    int i = blockIdx.x * blockDim.x + threadIdx.x;
    int stride = gridDim.x * blockDim.x;
    for (; i < E; i += stride) {
        int s, d; load_edge(p, i, E, is64, s, d);
        int pi = atomicAdd(&g_cur_in[d], 1);
        if (pi < CAP) g_csr_in[(size_t)d * CAP + pi] = s;
        int po = atomicAdd(&g_cur_out[s], 1);
        if (po < CAP) g_csr_out[(size_t)s * CAP + po] = d;
    }
}

// ---------------------------------------------------------------------------
// Pull aggregation: warp per (node, dir). Lane v-strided coalesced row loads.
// out row = [in-agg (D) | out-agg (D)], 2D wide.
template <int D>
__global__ void hop_kernel(const float* __restrict__ h, float* __restrict__ hn) {
    int gw   = (blockIdx.x * blockDim.x + threadIdx.x) >> 5;
    int lane = threadIdx.x & 31;
    if (gw >= 2 * NN) return;
    int n = gw >> 1;
    int dir = gw & 1;

    const int* lst = (dir ? g_csr_out : g_csr_in) + (size_t)n * CAP;
    int   deg = dir ? g_deg_out[n] : g_deg_in[n];
    float inv = dir ? g_inv_out[n] : g_inv_in[n];
    if (deg > CAP) deg = CAP;

    constexpr int V = D / 32;
    float acc[V];
#pragma unroll
    for (int v = 0; v < V; v++) acc[v] = 0.0f;

    for (int base = 0; base < deg; base += 32) {
        int nb = 0;
        if (base + lane < deg) nb = lst[base + lane];
        int cnt = min(32, deg - base);
        for (int j = 0; j < cnt; j++) {
            int s = __shfl_sync(0xffffffffu, nb, j);
            const float* row = h + (size_t)s * D;
#pragma unroll
            for (int v = 0; v < V; v++) acc[v] += __ldg(&row[v * 32 + lane]);
        }
    }

    float* o = hn + (size_t)n * (2 * D) + (size_t)dir * D;
#pragma unroll
    for (int v = 0; v < V; v++) o[v * 32 + lane] = acc[v] * inv;
}

// ---------------------------------------------------------------------------
// out[m,c] = sum_k A[m,k] * W[c,k] + b[c].  A:[M,512], W:[128,512] row-major.
// BM=64, BN=128, BK=32, 256 threads, 4x8 micro-tile per thread.
#define BM 64
#define BN 128
#define BK 32
__global__ __launch_bounds__(256) void gemm_kernel(
    const float* __restrict__ A, const float* __restrict__ W,
    const float* __restrict__ bias, float* __restrict__ out, int M) {
    __shared__ float As[BK][BM];
    __shared__ float Bs[BK][BN];

    int t  = threadIdx.x;
    int m0 = blockIdx.x * BM;
    int tm = (t & 15) * 4;   // 4 consecutive m
    int tn = (t >> 4) * 8;   // 8 consecutive n

    float acc[4][8];
#pragma unroll
    for (int i = 0; i < 4; i++)
#pragma unroll
        for (int j = 0; j < 8; j++) acc[i][j] = 0.0f;

    for (int k0 = 0; k0 < KDIM; k0 += BK) {
        // A tile: 64 x 32 floats = 512 float4, 2 per thread (transposed store)
#pragma unroll
        for (int r = 0; r < 2; r++) {
            int idx = t + r * 256;
            int m   = idx & 63;
            int k4  = idx >> 6;          // 0..7
            float4 v = make_float4(0.f, 0.f, 0.f, 0.f);
            if (m0 + m < M)
                v = *(const float4*)&A[(size_t)(m0 + m) * KDIM + k0 + k4 * 4];
            As[k4 * 4 + 0][m] = v.x; As[k4 * 4 + 1][m] = v.y;
            As[k4 * 4 + 2][m] = v.z; As[k4 * 4 + 3][m] = v.w;
        }
        // B tile: 128 x 32 floats = 1024 float4, 4 per thread
#pragma unroll
        for (int r = 0; r < 4; r++) {
            int idx = t + r * 256;
            int n   = idx & 127;
            int k4  = idx >> 7;          // 0..7
            float4 v = *(const float4*)&W[(size_t)n * KDIM + k0 + k4 * 4];
            Bs[k4 * 4 + 0][n] = v.x; Bs[k4 * 4 + 1][n] = v.y;
            Bs[k4 * 4 + 2][n] = v.z; Bs[k4 * 4 + 3][n] = v.w;
        }
        __syncthreads();
#pragma unroll
        for (int kk = 0; kk < BK; kk++) {
            float4 a  = *(const float4*)&As[kk][tm];
            float4 b0 = *(const float4*)&Bs[kk][tn];
            float4 b1 = *(const float4*)&Bs[kk][tn + 4];
            float av[4] = {a.x, a.y, a.z, a.w};
            float bv[8] = {b0.x, b0.y, b0.z, b0.w, b1.x, b1.y, b1.z, b1.w};
#pragma unroll
            for (int i = 0; i < 4; i++)
#pragma unroll
                for (int j = 0; j < 8; j++) acc[i][j] += av[i] * bv[j];
        }
        __syncthreads();
    }

    float bb[8];
#pragma unroll
    for (int j = 0; j < 8; j++) bb[j] = bias[tn + j];
#pragma unroll
    for (int i = 0; i < 4; i++) {
        int m = m0 + tm + i;
        if (m < M) {
            float4 o0 = make_float4(acc[i][0] + bb[0], acc[i][1] + bb[1],
                                    acc[i][2] + bb[2], acc[i][3] + bb[3]);
            float4 o1 = make_float4(acc[i][4] + bb[4], acc[i][5] + bb[5],
                                    acc[i][6] + bb[6], acc[i][7] + bb[7]);
            *(float4*)&out[(size_t)m * ODIM + tn]     = o0;
            *(float4*)&out[(size_t)m * ODIM + tn + 4] = o1;
        }
    }
}

// ---------------------------------------------------------------------------
extern "C" void kernel_launch(void* const* d_in, const int* in_sizes, int n_in,
                              void* d_out, int out_size) {
    const float* feature = (const float*)d_in[0];
    const int*   edges   = (const int*)d_in[1];   // int32 view; dtype detected
    const float* W       = (const float*)d_in[2];
    const float* b       = (const float*)d_in[3];
    float*       out     = (float*)d_out;

    const int N = in_sizes[0] / IND;      // 50000
    const int E = in_sizes[1] / 2;        // 800000

    const int T = 256;
    zero_kernel<<<(N + T - 1) / T, T>>>(N);
    detect_kernel<<<(E + T - 1) / T, T>>>(edges, E);
    degree_kernel<<<1024, T>>>(edges, E);
    inv_kernel<<<(N + T - 1) / T, T>>>(N);
    csr_kernel<<<1024, T>>>(edges, E);

    // 2*N warps -> 2*N*32 threads
    int hop_blocks = (2 * N * 32 + T - 1) / T;
    hop_kernel<64> <<<hop_blocks, T>>>(feature, g_h1);
    hop_kernel<128><<<hop_blocks, T>>>(g_h1, g_h2);
    hop_kernel<256><<<hop_blocks, T>>>(g_h2, g_h3);

    gemm_kernel<<<(N + BM - 1) / BM, 256>>>(g_h3, W, b, out, N);
}

// round 3
// speedup vs baseline: 1.1282x; 1.1282x over previous
#include <cuda_runtime.h>
#include <cstdint>

// ---------------------------------------------------------------------------
// LSAGEDirected: 3 directed mean-aggregation hops (64->128->256->512), then
// out = h3 @ W^T + b.
// R2 changes: neighbor-batched (x4) vectorized gathers in hop kernels;
// degree fused into CSR build; inv computed inline; hop64 positioned in the
// ncu-profiled launch slot.
// ---------------------------------------------------------------------------

#define NN 50000
#define CAP 96          // padded degree cap (Poisson(16); max ~45)
#define IND 64
#define KDIM 512
#define ODIM 128

// ---- static device scratch (allocation-free rule) ----
__device__ int   g_cur_in [NN];      // cursor == in-degree after build
__device__ int   g_cur_out[NN];
__device__ int   g_csr_in [(size_t)NN * CAP];
__device__ int   g_csr_out[(size_t)NN * CAP];
__device__ float g_h1[(size_t)NN * 128];
__device__ float g_h2[(size_t)NN * 256];
__device__ float g_h3[(size_t)NN * 512];
__device__ int   g_is64;

// ---------------------------------------------------------------------------
__global__ void zero_kernel(int n) {
    int i = blockIdx.x * blockDim.x + threadIdx.x;
    if (i < n) { g_cur_in[i] = 0; g_cur_out[i] = 0; }
    if (i == 0) g_is64 = 1;
}

// int32 data => some odd word (a real index) nonzero; int64 (<2^31) => all
// odd words are zero high-halves. Reads stay within both layouts' extents.
__global__ void detect_kernel(const int* __restrict__ p, int E) {
    int i = blockIdx.x * blockDim.x + threadIdx.x;
    int stride = gridDim.x * blockDim.x;
    for (; i < E; i += stride)
        if (p[2 * i + 1] != 0) { g_is64 = 0; return; }
}

// CSR build; atomic cursor doubles as degree counter.
__global__ void build_kernel(const int* __restrict__ p, int E) {
    int is64 = g_is64;
    int i = blockIdx.x * blockDim.x + threadIdx.x;
    int stride = gridDim.x * blockDim.x;
    for (; i < E; i += stride) {
        int s, d;
        if (is64) { s = p[2 * i]; d = p[2 * E + 2 * i]; }
        else      { s = p[i];     d = p[E + i]; }
        int pi = atomicAdd(&g_cur_in[d], 1);
        if (pi < CAP) g_csr_in[(size_t)d * CAP + pi] = s;
        int po = atomicAdd(&g_cur_out[s], 1);
        if (po < CAP) g_csr_out[(size_t)s * CAP + po] = d;
    }
}

// ---------------------------------------------------------------------------
// Hop kernels: one warp per (node, direction). Neighbor loop batched x4 so a
// single long-scoreboard wait covers 4 neighbors' loads. Vectorized gathers:
// D=64 -> float2/lane (256B row), D=128/256 -> float4/lane (512B chunks).

__global__ __launch_bounds__(256) void hop64_kernel(
    const float* __restrict__ h, float* __restrict__ hn) {
    int gw   = (blockIdx.x * blockDim.x + threadIdx.x) >> 5;
    int lane = threadIdx.x & 31;
    if (gw >= 2 * NN) return;
    int n = gw >> 1, dir = gw & 1;

    const int* lst = (dir ? g_csr_out : g_csr_in) + (size_t)n * CAP;
    int deg = dir ? g_cur_out[n] : g_cur_in[n];
    if (deg > CAP) deg = CAP;
    float inv = 1.0f / (float)max(deg, 1);

    float ax = 0.f, ay = 0.f;
    for (int base = 0; base < deg; base += 32) {
        int nb = 0;
        if (base + lane < deg) nb = lst[base + lane];
        int cnt = min(32, deg - base);
        int j = 0;
        for (; j + 4 <= cnt; j += 4) {
            int s0 = __shfl_sync(~0u, nb, j);
            int s1 = __shfl_sync(~0u, nb, j + 1);
            int s2 = __shfl_sync(~0u, nb, j + 2);
            int s3 = __shfl_sync(~0u, nb, j + 3);
            float2 r0 = *(const float2*)(h + (size_t)s0 * 64 + lane * 2);
            float2 r1 = *(const float2*)(h + (size_t)s1 * 64 + lane * 2);
            float2 r2 = *(const float2*)(h + (size_t)s2 * 64 + lane * 2);
            float2 r3 = *(const float2*)(h + (size_t)s3 * 64 + lane * 2);
            ax += (r0.x + r1.x) + (r2.x + r3.x);
            ay += (r0.y + r1.y) + (r2.y + r3.y);
        }
        for (; j < cnt; j++) {
            int s = __shfl_sync(~0u, nb, j);
            float2 r = *(const float2*)(h + (size_t)s * 64 + lane * 2);
            ax += r.x; ay += r.y;
        }
    }
    float2* o = (float2*)(hn + (size_t)n * 128 + dir * 64);
    o[lane] = make_float2(ax * inv, ay * inv);
}

template <int D>   // D = 128 or 256
__global__ __launch_bounds__(256) void hop_kernel(
    const float* __restrict__ h, float* __restrict__ hn) {
    constexpr int NV = D / 128;         // float4 chunks per lane
    int gw   = (blockIdx.x * blockDim.x + threadIdx.x) >> 5;
    int lane = threadIdx.x & 31;
    if (gw >= 2 * NN) return;
    int n = gw >> 1, dir = gw & 1;

    const int* lst = (dir ? g_csr_out : g_csr_in) + (size_t)n * CAP;
    int deg = dir ? g_cur_out[n] : g_cur_in[n];
    if (deg > CAP) deg = CAP;
    float inv = 1.0f / (float)max(deg, 1);

    float4 acc[NV];
#pragma unroll
    for (int v = 0; v < NV; v++) acc[v] = make_float4(0.f, 0.f, 0.f, 0.f);

    for (int base = 0; base < deg; base += 32) {
        int nb = 0;
        if (base + lane < deg) nb = lst[base + lane];
        int cnt = min(32, deg - base);
        int j = 0;
        for (; j + 4 <= cnt; j += 4) {
            int s0 = __shfl_sync(~0u, nb, j);
            int s1 = __shfl_sync(~0u, nb, j + 1);
            int s2 = __shfl_sync(~0u, nb, j + 2);
            int s3 = __shfl_sync(~0u, nb, j + 3);
#pragma unroll
            for (int v = 0; v < NV; v++) {
                float4 r0 = *(const float4*)(h + (size_t)s0 * D + v * 128 + lane * 4);
                float4 r1 = *(const float4*)(h + (size_t)s1 * D + v * 128 + lane * 4);
                float4 r2 = *(const float4*)(h + (size_t)s2 * D + v * 128 + lane * 4);
                float4 r3 = *(const float4*)(h + (size_t)s3 * D + v * 128 + lane * 4);
                acc[v].x += (r0.x + r1.x) + (r2.x + r3.x);
                acc[v].y += (r0.y + r1.y) + (r2.y + r3.y);
                acc[v].z += (r0.z + r1.z) + (r2.z + r3.z);
                acc[v].w += (r0.w + r1.w) + (r2.w + r3.w);
            }
        }
        for (; j < cnt; j++) {
            int s = __shfl_sync(~0u, nb, j);
#pragma unroll
            for (int v = 0; v < NV; v++) {
                float4 r = *(const float4*)(h + (size_t)s * D + v * 128 + lane * 4);
                acc[v].x += r.x; acc[v].y += r.y; acc[v].z += r.z; acc[v].w += r.w;
            }
        }
    }
    float* o = hn + (size_t)n * (2 * D) + (size_t)dir * D;
#pragma unroll
    for (int v = 0; v < NV; v++)
        *(float4*)(o + v * 128 + lane * 4) =
            make_float4(acc[v].x * inv, acc[v].y * inv, acc[v].z * inv, acc[v].w * inv);
}

// ---------------------------------------------------------------------------
// out[m,c] = sum_k A[m,k] * W[c,k] + b[c].  A:[M,512], W:[128,512] row-major.
#define BM 64
#define BN 128
#define BK 32
__global__ __launch_bounds__(256) void gemm_kernel(
    const float* __restrict__ A, const float* __restrict__ W,
    const float* __restrict__ bias, float* __restrict__ out, int M) {
    __shared__ float As[BK][BM];
    __shared__ float Bs[BK][BN];

    int t  = threadIdx.x;
    int m0 = blockIdx.x * BM;
    int tm = (t & 15) * 4;
    int tn = (t >> 4) * 8;

    float acc[4][8];
#pragma unroll
    for (int i = 0; i < 4; i++)
#pragma unroll
        for (int j = 0; j < 8; j++) acc[i][j] = 0.0f;

    for (int k0 = 0; k0 < KDIM; k0 += BK) {
#pragma unroll
        for (int r = 0; r < 2; r++) {
            int idx = t + r * 256;
            int m   = idx & 63;
            int k4  = idx >> 6;
            float4 v = make_float4(0.f, 0.f, 0.f, 0.f);
            if (m0 + m < M)
                v = *(const float4*)&A[(size_t)(m0 + m) * KDIM + k0 + k4 * 4];
            As[k4 * 4 + 0][m] = v.x; As[k4 * 4 + 1][m] = v.y;
            As[k4 * 4 + 2][m] = v.z; As[k4 * 4 + 3][m] = v.w;
        }
#pragma unroll
        for (int r = 0; r < 4; r++) {
            int idx = t + r * 256;
            int n   = idx & 127;
            int k4  = idx >> 7;
            float4 v = *(const float4*)&W[(size_t)n * KDIM + k0 + k4 * 4];
            Bs[k4 * 4 + 0][n] = v.x; Bs[k4 * 4 + 1][n] = v.y;
            Bs[k4 * 4 + 2][n] = v.z; Bs[k4 * 4 + 3][n] = v.w;
        }
        __syncthreads();
#pragma unroll
        for (int kk = 0; kk < BK; kk++) {
            float4 a  = *(const float4*)&As[kk][tm];
            float4 b0 = *(const float4*)&Bs[kk][tn];
            float4 b1 = *(const float4*)&Bs[kk][tn + 4];
            float av[4] = {a.x, a.y, a.z, a.w};
            float bv[8] = {b0.x, b0.y, b0.z, b0.w, b1.x, b1.y, b1.z, b1.w};
#pragma unroll
            for (int i = 0; i < 4; i++)
#pragma unroll
                for (int j = 0; j < 8; j++) acc[i][j] += av[i] * bv[j];
        }
        __syncthreads();
    }

    float bb[8];
#pragma unroll
    for (int j = 0; j < 8; j++) bb[j] = bias[tn + j];
#pragma unroll
    for (int i = 0; i < 4; i++) {
        int m = m0 + tm + i;
        if (m < M) {
            float4 o0 = make_float4(acc[i][0] + bb[0], acc[i][1] + bb[1],
                                    acc[i][2] + bb[2], acc[i][3] + bb[3]);
            float4 o1 = make_float4(acc[i][4] + bb[4], acc[i][5] + bb[5],
                                    acc[i][6] + bb[6], acc[i][7] + bb[7]);
            *(float4*)&out[(size_t)m * ODIM + tn]     = o0;
            *(float4*)&out[(size_t)m * ODIM + tn + 4] = o1;
        }
    }
}

// ---------------------------------------------------------------------------
extern "C" void kernel_launch(void* const* d_in, const int* in_sizes, int n_in,
                              void* d_out, int out_size) {
    const float* feature = (const float*)d_in[0];
    const int*   edges   = (const int*)d_in[1];
    const float* W       = (const float*)d_in[2];
    const float* b       = (const float*)d_in[3];
    float*       out     = (float*)d_out;

    const int N = in_sizes[0] / IND;   // 50000
    const int E = in_sizes[1] / 2;     // 800000

    const int T = 256;
    zero_kernel  <<<(N + T - 1) / T, T>>>(N);        // launch 1
    detect_kernel<<<1024, T>>>(edges, E);            // launch 2
    build_kernel <<<2048, T>>>(edges, E);            // launch 3

    int hop_blocks = (2 * N * 32 + T - 1) / T;       // 12500
    hop64_kernel   <<<hop_blocks, T>>>(feature, g_h1);  // launch 4 <- profiled
    hop_kernel<128><<<hop_blocks, T>>>(g_h1, g_h2);     // launch 5
    hop_kernel<256><<<hop_blocks, T>>>(g_h2, g_h3);     // launch 6

    gemm_kernel<<<(N + BM - 1) / BM, 256>>>(g_h3, W, b, out, N);  // launch 7
}

// round 5
// speedup vs baseline: 1.1397x; 1.0103x over previous
#include <cuda_runtime.h>
#include <cstdint>

// ---------------------------------------------------------------------------
// LSAGEDirected: 3 directed mean-aggregation hops (64->128->256->512), then
// out = h3 @ W^T + b.
// R3: fused init+detect (monotone is32 flag); chunk-parallel hop kernels
// (warp per (node,dir,128-float chunk)); 8-wide neighbor batching; launch
// order arranged so the ncu slot (my 4th launch) profiles hop128.
// ---------------------------------------------------------------------------

#define NN 50000
#define CAP 96          // padded degree cap (Poisson(16); max ~45)
#define IND 64
#define KDIM 512
#define ODIM 128

// ---- static device scratch (allocation-free rule) ----
__device__ int   g_cur_in [NN];      // cursor == in-degree after build
__device__ int   g_cur_out[NN];
__device__ int   g_csr_in [(size_t)NN * CAP];
__device__ int   g_csr_out[(size_t)NN * CAP];
__device__ float g_h1[(size_t)NN * 128];
__device__ float g_h2[(size_t)NN * 256];
__device__ float g_h3[(size_t)NN * 512];
// Monotone dtype flag: 0 = int64 (default), 1 = int32. Only ever set to 1
// when edge data is int32; value depends solely on input data, so replays
// are idempotent (no reset needed).
__device__ int   g_is32;

// ---------------------------------------------------------------------------
// Launch 1: zero cursors + detect edge dtype.
// int32 data => some odd 32-bit word (a real index, ~always nonzero) exists;
// int64 (<2^31 values) => all odd words are zero high-halves.
__global__ void init_kernel(const int* __restrict__ p, int E, int N) {
    int i = blockIdx.x * blockDim.x + threadIdx.x;
    int stride = gridDim.x * blockDim.x;
    for (int j = i; j < N; j += stride) { g_cur_in[j] = 0; g_cur_out[j] = 0; }
    for (int j = i; j < E; j += stride) {
        if (p[2 * j + 1] != 0) { g_is32 = 1; break; }
    }
}

// Launch 2: CSR build; atomic cursor doubles as degree counter.
__global__ void build_kernel(const int* __restrict__ p, int E) {
    int is32 = g_is32;
    int i = blockIdx.x * blockDim.x + threadIdx.x;
    int stride = gridDim.x * blockDim.x;
    for (; i < E; i += stride) {
        int s, d;
        if (is32) { s = p[i];     d = p[E + i]; }
        else      { s = p[2 * i]; d = p[2 * E + 2 * i]; }
        int pi = atomicAdd(&g_cur_in[d], 1);
        if (pi < CAP) g_csr_in[(size_t)d * CAP + pi] = s;
        int po = atomicAdd(&g_cur_out[s], 1);
        if (po < CAP) g_csr_out[(size_t)s * CAP + po] = d;
    }
}

// ---------------------------------------------------------------------------
// Launch 3: hop64. One warp per (node,dir); float2 row gathers (256B rows);
// neighbors batched x8 so one long-scoreboard wait covers 8 gathers.
__global__ __launch_bounds__(256) void hop64_kernel(
    const float* __restrict__ h, float* __restrict__ hn) {
    int gw   = (blockIdx.x * blockDim.x + threadIdx.x) >> 5;
    int lane = threadIdx.x & 31;
    if (gw >= 2 * NN) return;
    int n = gw >> 1, dir = gw & 1;

    const int* lst = (dir ? g_csr_out : g_csr_in) + (size_t)n * CAP;
    int deg = dir ? g_cur_out[n] : g_cur_in[n];
    if (deg > CAP) deg = CAP;
    float inv = 1.0f / (float)max(deg, 1);

    float ax = 0.f, ay = 0.f;
    for (int base = 0; base < deg; base += 32) {
        int nb = 0;
        if (base + lane < deg) nb = lst[base + lane];
        int cnt = min(32, deg - base);
        int j = 0;
        for (; j + 8 <= cnt; j += 8) {
            float2 r[8];
#pragma unroll
            for (int q = 0; q < 8; q++) {
                int s = __shfl_sync(~0u, nb, j + q);
                r[q] = *(const float2*)(h + (size_t)s * 64 + lane * 2);
            }
#pragma unroll
            for (int q = 0; q < 8; q++) { ax += r[q].x; ay += r[q].y; }
        }
        for (; j < cnt; j++) {
            int s = __shfl_sync(~0u, nb, j);
            float2 r = *(const float2*)(h + (size_t)s * 64 + lane * 2);
            ax += r.x; ay += r.y;
        }
    }
    float2* o = (float2*)(hn + (size_t)n * 128 + dir * 64);
    o[lane] = make_float2(ax * inv, ay * inv);
}

// Launches 4,5: hop128 / hop256. One warp per (node, dir, 128-float chunk):
// each warp gathers a 512B slice (float4/lane) of each neighbor row.
template <int D>   // 128 or 256
__global__ __launch_bounds__(256) void hop_chunk_kernel(
    const float* __restrict__ h, float* __restrict__ hn) {
    constexpr int C = D / 128;          // chunks per (node,dir)
    int gw   = (blockIdx.x * blockDim.x + threadIdx.x) >> 5;
    int lane = threadIdx.x & 31;
    if (gw >= 2 * NN * C) return;
    int chunk = gw % C;                 // adjacent warps share (n,dir) -> CSR L1 hits
    int rem   = gw / C;
    int dir   = rem & 1;
    int n     = rem >> 1;

    const int* lst = (dir ? g_csr_out : g_csr_in) + (size_t)n * CAP;
    int deg = dir ? g_cur_out[n] : g_cur_in[n];
    if (deg > CAP) deg = CAP;
    float inv = 1.0f / (float)max(deg, 1);

    const float* hc = h + (size_t)chunk * 128;   // column offset into D-wide rows
    float4 acc = make_float4(0.f, 0.f, 0.f, 0.f);

    for (int base = 0; base < deg; base += 32) {
        int nb = 0;
        if (base + lane < deg) nb = lst[base + lane];
        int cnt = min(32, deg - base);
        int j = 0;
        for (; j + 8 <= cnt; j += 8) {
            float4 r[8];
#pragma unroll
            for (int q = 0; q < 8; q++) {
                int s = __shfl_sync(~0u, nb, j + q);
                r[q] = *(const float4*)(hc + (size_t)s * D + lane * 4);
            }
#pragma unroll
            for (int q = 0; q < 8; q++) {
                acc.x += r[q].x; acc.y += r[q].y;
                acc.z += r[q].z; acc.w += r[q].w;
            }
        }
        for (; j < cnt; j++) {
            int s = __shfl_sync(~0u, nb, j);
            float4 r = *(const float4*)(hc + (size_t)s * D + lane * 4);
            acc.x += r.x; acc.y += r.y; acc.z += r.z; acc.w += r.w;
        }
    }
    float* o = hn + (size_t)n * (2 * D) + (size_t)dir * D + (size_t)chunk * 128;
    *(float4*)(o + lane * 4) =
        make_float4(acc.x * inv, acc.y * inv, acc.z * inv, acc.w * inv);
}

// ---------------------------------------------------------------------------
// Launch 6: out[m,c] = sum_k A[m,k]*W[c,k] + b[c].  A:[M,512], W:[128,512].
#define BM 64
#define BN 128
#define BK 32
__global__ __launch_bounds__(256) void gemm_kernel(
    const float* __restrict__ A, const float* __restrict__ W,
    const float* __restrict__ bias, float* __restrict__ out, int M) {
    __shared__ float As[BK][BM];
    __shared__ float Bs[BK][BN];

    int t  = threadIdx.x;
    int m0 = blockIdx.x * BM;
    int tm = (t & 15) * 4;
    int tn = (t >> 4) * 8;

    float acc[4][8];
#pragma unroll
    for (int i = 0; i < 4; i++)
#pragma unroll
        for (int j = 0; j < 8; j++) acc[i][j] = 0.0f;

    for (int k0 = 0; k0 < KDIM; k0 += BK) {
#pragma unroll
        for (int r = 0; r < 2; r++) {
            int idx = t + r * 256;
            int m   = idx & 63;
            int k4  = idx >> 6;
            float4 v = make_float4(0.f, 0.f, 0.f, 0.f);
            if (m0 + m < M)
                v = *(const float4*)&A[(size_t)(m0 + m) * KDIM + k0 + k4 * 4];
            As[k4 * 4 + 0][m] = v.x; As[k4 * 4 + 1][m] = v.y;
            As[k4 * 4 + 2][m] = v.z; As[k4 * 4 + 3][m] = v.w;
        }
#pragma unroll
        for (int r = 0; r < 4; r++) {
            int idx = t + r * 256;
            int n   = idx & 127;
            int k4  = idx >> 7;
            float4 v = *(const float4*)&W[(size_t)n * KDIM + k0 + k4 * 4];
            Bs[k4 * 4 + 0][n] = v.x; Bs[k4 * 4 + 1][n] = v.y;
            Bs[k4 * 4 + 2][n] = v.z; Bs[k4 * 4 + 3][n] = v.w;
        }
        __syncthreads();
#pragma unroll
        for (int kk = 0; kk < BK; kk++) {
            float4 a  = *(const float4*)&As[kk][tm];
            float4 b0 = *(const float4*)&Bs[kk][tn];
            float4 b1 = *(const float4*)&Bs[kk][tn + 4];
            float av[4] = {a.x, a.y, a.z, a.w};
            float bv[8] = {b0.x, b0.y, b0.z, b0.w, b1.x, b1.y, b1.z, b1.w};
#pragma unroll
            for (int i = 0; i < 4; i++)
#pragma unroll
                for (int j = 0; j < 8; j++) acc[i][j] += av[i] * bv[j];
        }
        __syncthreads();
    }

    float bb[8];
#pragma unroll
    for (int j = 0; j < 8; j++) bb[j] = bias[tn + j];
#pragma unroll
    for (int i = 0; i < 4; i++) {
        int m = m0 + tm + i;
        if (m < M) {
            float4 o0 = make_float4(acc[i][0] + bb[0], acc[i][1] + bb[1],
                                    acc[i][2] + bb[2], acc[i][3] + bb[3]);
            float4 o1 = make_float4(acc[i][4] + bb[4], acc[i][5] + bb[5],
                                    acc[i][6] + bb[6], acc[i][7] + bb[7]);
            *(float4*)&out[(size_t)m * ODIM + tn]     = o0;
            *(float4*)&out[(size_t)m * ODIM + tn + 4] = o1;
        }
    }
}

// ---------------------------------------------------------------------------
extern "C" void kernel_launch(void* const* d_in, const int* in_sizes, int n_in,
                              void* d_out, int out_size) {
    const float* feature = (const float*)d_in[0];
    const int*   edges   = (const int*)d_in[1];
    const float* W       = (const float*)d_in[2];
    const float* b       = (const float*)d_in[3];
    float*       out     = (float*)d_out;

    const int N = in_sizes[0] / IND;   // 50000
    const int E = in_sizes[1] / 2;     // 800000

    const int T = 256;
    init_kernel <<<1024, T>>>(edges, E, N);                       // launch 1
    build_kernel<<<2048, T>>>(edges, E);                          // launch 2

    int w64  = 2 * NN;          // warps for hop64
    int w128 = 2 * NN;          // warps for hop128 (C=1)
    int w256 = 2 * NN * 2;      // warps for hop256 (C=2)
    hop64_kernel          <<<(w64  * 32 + T - 1) / T, T>>>(feature, g_h1); // 3
    hop_chunk_kernel<128> <<<(w128 * 32 + T - 1) / T, T>>>(g_h1, g_h2);    // 4 <- profiled
    hop_chunk_kernel<256> <<<(w256 * 32 + T - 1) / T, T>>>(g_h2, g_h3);    // 5

    gemm_kernel<<<(N + BM - 1) / BM, 256>>>(g_h3, W, b, out, N);           // 6
}